// round 8
// baseline (speedup 1.0000x reference)
#include <cuda_runtime.h>
#include <math.h>
#include <float.h>

#define NN   8400
#define CC   80
#define RB   17      // REG_MAX+1 bins
#define KTOP 13
#define EPSF 1e-9f
#define MAXB 32
#define MAXM 96
#define CAP  1536
#define CORR_SPLIT 4
#define DEC_BLKS 525
#define CLS_BLKS 1024

// ---------------- scratch (static device globals; all zero-init) ----------
__device__ float4             g_boxes4[MAXB * NN];
__device__ unsigned long long g_key[MAXB * NN];     // (metric_bits<<32)|(~m); self-cleaned
__device__ int                g_tk_n[MAXB * MAXM * KTOP];
__device__ float              g_tk_v[MAXB * MAXM * KTOP];
__device__ float              g_gt_mm[MAXB * MAXM];
__device__ float              g_gt_mi[MAXB * MAXM];
__device__ int                g_fgl[MAXB * MAXM * KTOP];           // pick anchor idx
__device__ unsigned long long g_fgv[MAXB * MAXM * KTOP];           // pick key
__device__ int                g_fgcnt;
__device__ int                g_done;
__device__ double             g_acc[8]; // 0 cls_base, 1 cls_corr, 2 score_sum, 3 iou, 4 dfl, 5 npos

__device__ __forceinline__ void warp_add(double v, double* gaddr) {
#pragma unroll
    for (int off = 16; off; off >>= 1)
        v += __shfl_down_sync(0xFFFFFFFFu, v, off);
    if ((threadIdx.x & 31) == 0) atomicAdd(gaddr, v);
}
__device__ __forceinline__ void sig_bce0(float x, float& sg, float& bce0) {
    float u = __expf(-fabsf(x));
    float r = __fdividef(1.f, 1.f + u);
    sg   = (x >= 0.f) ? r : 1.f - r;
    bce0 = fmaxf(x, 0.f) + __logf(1.f + u);
}

// ---------------- K1: bulk = DFL decode | base VFL (block-partitioned) ----
__global__ void k_bulk(const float* __restrict__ pd, const float* __restrict__ ap,
                       const float4* __restrict__ s4, int total, long total4) {
    if (blockIdx.x < DEC_BLKS) {
        int an = blockIdx.x * blockDim.x + threadIdx.x;
        if (an >= total) return;
        int n = an % NN;
        const float4* row4 = (const float4*)(pd + (size_t)an * (4 * RB));
        float r[4 * RB];
#pragma unroll
        for (int j = 0; j < RB; j++) {
            float4 v = row4[j];
            r[4 * j] = v.x; r[4 * j + 1] = v.y; r[4 * j + 2] = v.z; r[4 * j + 3] = v.w;
        }
        float d[4];
#pragma unroll
        for (int s = 0; s < 4; s++) {
            float mx = r[RB * s];
#pragma unroll
            for (int j = 1; j < RB; j++) mx = fmaxf(mx, r[RB * s + j]);
            float se = 0.f, ws = 0.f;
#pragma unroll
            for (int j = 0; j < RB; j++) {
                float e = __expf(r[RB * s + j] - mx);
                se += e; ws = fmaf(e, (float)j, ws);
            }
            d[s] = __fdividef(ws, se);
        }
        float axp = ap[2 * n], ayp = ap[2 * n + 1];
        float4 o; o.x = axp - d[0]; o.y = ayp - d[1]; o.z = axp + d[2]; o.w = ayp + d[3];
        g_boxes4[an] = o;
    } else {
        __shared__ double red[8];
        float acc = 0.f;
        long stride = (long)CLS_BLKS * blockDim.x;
        for (long i = (long)(blockIdx.x - DEC_BLKS) * blockDim.x + threadIdx.x;
             i < total4; i += stride) {
            float4 v = s4[i];
            float xs[4] = { v.x, v.y, v.z, v.w };
#pragma unroll
            for (int j = 0; j < 4; j++) {
                float sg, bb;
                sig_bce0(xs[j], sg, bb);
                acc = fmaf(sg * sg, bb, acc);
            }
        }
        double dv = (double)acc;
#pragma unroll
        for (int off = 16; off; off >>= 1)
            dv += __shfl_down_sync(0xFFFFFFFFu, dv, off);
        if ((threadIdx.x & 31) == 0) red[threadIdx.x >> 5] = dv;
        __syncthreads();
        if (threadIdx.x < 32) {
            double w = (threadIdx.x < 8) ? red[threadIdx.x] : 0.0;
#pragma unroll
            for (int off = 4; off; off >>= 1)
                w += __shfl_down_sync(0xFFFFFFFFu, w, off);
            if (threadIdx.x == 0) atomicAdd(&g_acc[0], 0.75 * w);
        }
    }
}

// ---------------- K2: TAL assignment, one block per (b,m) -----------------
// Anchor grid is the fixed YOLO layout: level l has nl x nl anchors at
// stride sf, coord (i+0.5)*sf (exact in fp32: sf is a power of two).
__global__ void k_assign(const float* __restrict__ scores,
                         const int* __restrict__ gtl, const float* __restrict__ gtb,
                         const float* __restrict__ mgt, int M) {
    __shared__ float s_iou[CAP];
    __shared__ unsigned long long s_key[CAP];
    __shared__ int   s_cnt;
    __shared__ int                pk_i[KTOP];
    __shared__ unsigned long long pk_k[KTOP];

    int b = blockIdx.x / M, m = blockIdx.x % M;
    int base = b * M + m;
    if (threadIdx.x == 0) s_cnt = 0;
    __syncthreads();

    float mg  = mgt[base];
    float gx1 = gtb[base * 4 + 0], gy1 = gtb[base * 4 + 1];
    float gx2 = gtb[base * 4 + 2], gy2 = gtb[base * 4 + 3];
    float ga  = (gx2 - gx1) * (gy2 - gy1);
    int   lbl = min(max(gtl[base], 0), CC - 1);

    const int   nlv[3] = { 80, 40, 20 };
    const int   off[3] = { 0, 6400, 8000 };
    const float sfv[3] = { 8.f, 16.f, 32.f };

    // per-level candidate rectangles (superset; exact test applied below)
    int xlo[3], ylo[3], wx[3], cbase[4];
    cbase[0] = 0;
#pragma unroll
    for (int l = 0; l < 3; l++) {
        float inv_s = 1.f / sfv[l];
        int n1 = nlv[l] - 1;
        int x0 = min(max((int)floorf(gx1 * inv_s - 0.5f), 0), n1);
        int x1 = min(max((int)ceilf (gx2 * inv_s - 0.5f), 0), n1);
        int y0 = min(max((int)floorf(gy1 * inv_s - 0.5f), 0), n1);
        int y1 = min(max((int)ceilf (gy2 * inv_s - 0.5f), 0), n1);
        xlo[l] = x0; ylo[l] = y0; wx[l] = x1 - x0 + 1;
        int cl = (mg != 0.f) ? wx[l] * (y1 - y0 + 1) : 0;
        cbase[l + 1] = cbase[l] + cl;
    }
    int ctot = cbase[3];

    // fused candidate pass: exact inside test -> iou -> score -> packed key
    for (int t = threadIdx.x; t < ctot; t += blockDim.x) {
        int l = (t >= cbase[1]) + (t >= cbase[2]);
        int j = t - cbase[l];
        int ix = xlo[l] + j % wx[l];
        int iy = ylo[l] + j / wx[l];
        float s  = sfv[l];
        float ax = ((float)ix + 0.5f) * s;
        float ay = ((float)iy + 0.5f) * s;
        float mind = fminf(fminf(ax - gx1, ay - gy1), fminf(gx2 - ax, gy2 - ay));
        if (!(mind > EPSF)) continue;
        int n = off[l] + iy * nlv[l] + ix;
        float4 pb = g_boxes4[(size_t)b * NN + n];
        float iw = fminf(pb.z, gx2) - fmaxf(pb.x, gx1);
        float ih = fminf(pb.w, gy2) - fmaxf(pb.y, gy1);
        if (iw <= 0.f || ih <= 0.f) continue;
        float inter = iw * ih;
        float pa = (pb.z - pb.x) * (pb.w - pb.y);
        float iou = __fdividef(inter, pa + ga - inter + EPSF);
        float x = scores[((size_t)b * NN + n) * CC + lbl];
        float u  = __expf(-fabsf(x));
        float r  = __fdividef(1.f, 1.f + u);
        float sc = (x >= 0.f) ? r : 1.f - r;
        float i2 = iou * iou;
        float met = sc * i2 * i2 * i2 * mg;
        if (met > 0.f) {
            int slot = atomicAdd(&s_cnt, 1);
            if (slot < CAP) {
                s_iou[slot] = iou;
                s_key[slot] = ((unsigned long long)__float_as_uint(met) << 32) |
                              (unsigned long long)(0xFFFFFFFFu - (unsigned)n);
            }
        }
    }
    __syncthreads();
    int cnt = min(s_cnt, CAP);

    // warp-0 top-k on packed keys (desc met, asc n)
    if (threadIdx.x < 32) {
        int lane = threadIdx.x;
        unsigned long long pkey = ~0ull;
        float mm = 0.f, mi = 0.f;
        int npk = 0;
        for (int k = 0; k < KTOP; k++) {
            unsigned long long bk = 0ull; int bi = -1;
            for (int j = lane; j < cnt; j += 32) {
                unsigned long long kk = s_key[j];
                if (kk < pkey && kk > bk) { bk = kk; bi = j; }
            }
#pragma unroll
            for (int off2 = 16; off2; off2 >>= 1) {
                unsigned long long k2 = __shfl_down_sync(0xFFFFFFFFu, bk, off2);
                int               i2 = __shfl_down_sync(0xFFFFFFFFu, bi, off2);
                if (k2 > bk) { bk = k2; bi = i2; }
            }
            bk = __shfl_sync(0xFFFFFFFFu, bk, 0);
            bi = __shfl_sync(0xFFFFFFFFu, bi, 0);
            bool valid = (bk >> 32) != 0ull;
            if (lane == 0) {
                if (valid) {
                    float met = __uint_as_float((unsigned)(bk >> 32));
                    int   n   = (int)(0xFFFFFFFFu - (unsigned)(bk & 0xFFFFFFFFull));
                    g_tk_v[base * KTOP + k] = met;
                    g_tk_n[base * KTOP + k] = n;
                    if (k == 0) mm = met;
                    mi = fmaxf(mi, s_iou[bi]);
                    unsigned long long mkey =
                        (bk & 0xFFFFFFFF00000000ull) |
                        (unsigned long long)(0xFFFFFFFFu - (unsigned)m);
                    atomicMax(&g_key[(size_t)b * NN + n], mkey);
                    pk_i[npk] = b * NN + n;
                    pk_k[npk] = mkey;
                    npk++;
                } else {
                    g_tk_v[base * KTOP + k] = 0.f;
                    g_tk_n[base * KTOP + k] = -1;
                }
            }
            if (valid) pkey = bk;
        }
        npk = __shfl_sync(0xFFFFFFFFu, npk, 0);
        int base2 = 0;
        if (lane == 0) {
            g_gt_mm[base] = mm; g_gt_mi[base] = mi;
            base2 = atomicAdd(&g_fgcnt, npk);
        }
        base2 = __shfl_sync(0xFFFFFFFFu, base2, 0);
        __syncwarp();
        if (lane < npk) {
            g_fgl[base2 + lane] = pk_i[lane];
            g_fgv[base2 + lane] = pk_k[lane];
        }
    }
}

// ---------------- K3: post = GIoU+DFL | VFL corrections | finalize --------
__global__ void k_post(const float* __restrict__ pd, const float* __restrict__ ap,
                       const float* __restrict__ scores, const int* __restrict__ gtl,
                       const float* __restrict__ gtb, int M, int fgblks, float* out) {
    if ((int)blockIdx.x < fgblks) {
        int t = blockIdx.x * blockDim.x + threadIdx.x;
        double li = 0.0, ldf = 0.0, np = 0.0;
        if (t < g_fgcnt) {
            int i = g_fgl[t];
            unsigned long long mykey = g_fgv[t];
            if (g_key[i] == mykey) {                 // this pick is the argmax winner
                np = 1.0;
                int b = i / NN, n = i % NN;
                unsigned mstar = 0xFFFFFFFFu - (unsigned)(mykey & 0xFFFFFFFFull);
                const float* gt = &gtb[((size_t)b * M + mstar) * 4];
                float tx1 = gt[0], ty1 = gt[1], tx2 = gt[2], ty2 = gt[3];
                float4 p = g_boxes4[i];
                float iw = fminf(p.z, tx2) - fmaxf(p.x, tx1);
                float ih = fminf(p.w, ty2) - fmaxf(p.y, ty1);
                float inter = fmaxf(iw, 0.f) * fmaxf(ih, 0.f);
                float a1 = (p.z - p.x) * (p.w - p.y);
                float a2 = (tx2 - tx1) * (ty2 - ty1);
                float uni = a1 + a2 - inter;
                float iou = __fdividef(inter, uni + 1e-9f);
                float enc = (fmaxf(p.z, tx2) - fminf(p.x, tx1)) *
                            (fmaxf(p.w, ty2) - fminf(p.y, ty1));
                float giou = iou - __fdividef(enc - uni, enc + 1e-9f);
                li = (double)(1.f - giou);

                float axp = ap[2 * n], ayp = ap[2 * n + 1];
                float tt[4] = { axp - tx1, ayp - ty1, tx2 - axp, ty2 - ayp };
                const float4* row4 = (const float4*)(pd + (size_t)i * (4 * RB));
                float r[4 * RB];
#pragma unroll
                for (int j = 0; j < RB; j++) {
                    float4 v = row4[j];
                    r[4 * j] = v.x; r[4 * j + 1] = v.y; r[4 * j + 2] = v.z; r[4 * j + 3] = v.w;
                }
                float dfl = 0.f;
#pragma unroll
                for (int s = 0; s < 4; s++) {
                    float tv = fminf(fmaxf(tt[s], 0.f), 15.99f);
                    int tl = (int)floorf(tv);
                    float wr = tv - (float)tl, wl = 1.f - wr;
                    float mx = r[RB * s];
#pragma unroll
                    for (int j = 1; j < RB; j++) mx = fmaxf(mx, r[RB * s + j]);
                    float se = 0.f;
#pragma unroll
                    for (int j = 0; j < RB; j++) se += __expf(r[RB * s + j] - mx);
                    float lse = mx + __logf(se);
                    float cl = pd[(size_t)i * (4 * RB) + RB * s + tl];
                    float cr = pd[(size_t)i * (4 * RB) + RB * s + tl + 1];
                    dfl += (lse - cl) * wl + (lse - cr) * wr;
                }
                ldf = (double)dfl;
            }
        }
        warp_add(li,  &g_acc[3]);
        warp_add(ldf, &g_acc[4]);
        warp_add(np,  &g_acc[5]);
    } else {
        __shared__ float e_s[MAXM * KTOP];
        __shared__ int   e_nc[MAXM * KTOP];
        int pb   = blockIdx.x - fgblks;
        int b    = pb / CORR_SPLIT;
        int part = pb % CORR_SPLIT;
        int tot  = M * KTOP;

        for (int i = threadIdx.x; i < tot; i += blockDim.x) {
            int mm = i / KTOP;
            int gi = (b * M + mm) * KTOP + (i % KTOP);
            float met = g_tk_v[gi];
            float s = -1.f; int nc = -1;
            if (met > 0.f) {
                s  = __fdividef(met, g_gt_mm[b * M + mm] + EPSF) * g_gt_mi[b * M + mm];
                nc = (g_tk_n[gi] << 7) | min(max(gtl[b * M + mm], 0), CC - 1);
            }
            e_s[i] = s; e_nc[i] = nc;
        }
        __syncthreads();

        int per = (tot + CORR_SPLIT - 1) / CORR_SPLIT;
        int lo = part * per, hi = min(lo + per, tot);
        double corr = 0.0, ssum = 0.0;
        for (int i = lo + threadIdx.x; i < hi; i += blockDim.x) {
            float s = e_s[i];
            if (s < 0.f) continue;
            int nc = e_nc[i];
            bool owner = true;
            for (int j = 0; j < tot; j++) {
                if (j == i || e_nc[j] != nc) continue;
                float sj = e_s[j];
                if (sj > s || (sj == s && j < i)) { owner = false; break; }
            }
            if (!owner) continue;
            int n = nc >> 7, c = nc & 127;
            unsigned long long key = g_key[(size_t)b * NN + n];
            unsigned mstar = 0xFFFFFFFFu - (unsigned)(key & 0xFFFFFFFFull);
            int albl = min(max(gtl[b * M + mstar], 0), CC - 1);
            float x = scores[((size_t)b * NN + n) * CC + c];
            float sg, bce0;
            sig_bce0(x, sg, bce0);
            float bce = bce0 - x * s;
            float wb  = 0.75f * sg * sg;
            float w   = (albl == c) ? s : wb;
            corr += (double)(w * bce) - (double)(wb * bce0);
            ssum += (double)s;
        }
        warp_add(corr, &g_acc[1]);
        warp_add(ssum, &g_acc[2]);
    }

    // ---- last-block finalize + self-clean (replaces k_final) ----
    __shared__ int s_last;
    __threadfence();
    __syncthreads();
    if (threadIdx.x == 0) {
        int ticket = atomicAdd(&g_done, 1);
        s_last = (ticket == (int)gridDim.x - 1);
    }
    __syncthreads();
    if (!s_last) return;
    __threadfence();   // acquire all blocks' atomics
    if (threadIdx.x == 0) {
        volatile double* a = g_acc;
        double np = a[5] < 1.0 ? 1.0 : a[5];
        double ss = a[2] < 1.0 ? 1.0 : a[2];
        double loss = (a[0] + a[1]) / ss
                    + 2.5 * a[3] / np
                    + 0.5 * a[4] / (np * 4.0);
        out[0] = (float)loss;
    }
    __syncthreads();
    int fcnt = g_fgcnt;
    for (int t = threadIdx.x; t < fcnt; t += blockDim.x)
        g_key[g_fgl[t]] = 0ull;                        // clean touched keys
    __syncthreads();
    if (threadIdx.x < 8) g_acc[threadIdx.x] = 0.0;     // reset accumulators
    if (threadIdx.x == 8) g_fgcnt = 0;
    if (threadIdx.x == 9) g_done = 0;
}

// ---------------- launcher (3 launches) -----------------------------------
extern "C" void kernel_launch(void* const* d_in, const int* in_sizes, int n_in,
                              void* d_out, int out_size) {
    const float* scores = (const float*)d_in[0];
    const float* pdist  = (const float*)d_in[1];
    const float* ap     = (const float*)d_in[2];
    const int*   gtl    = (const int*)d_in[3];
    const float* gtb    = (const float*)d_in[4];
    const float* mgt    = (const float*)d_in[5];

    int B = in_sizes[0] / (NN * CC);
    int M = in_sizes[4] / (B * 4);
    int total = B * NN;
    long total4 = (long)total * CC / 4;
    int maxfg  = B * M * KTOP;
    int fgblks = (maxfg + 255) / 256;

    k_bulk<<<DEC_BLKS + CLS_BLKS, 256>>>(pdist, ap, (const float4*)scores, total, total4);
    k_assign<<<B * M, 256>>>(scores, gtl, gtb, mgt, M);
    k_post<<<fgblks + B * CORR_SPLIT, 256>>>(pdist, ap, scores, gtl, gtb, M, fgblks, (float*)d_out);
}

// round 9
// speedup vs baseline: 1.4862x; 1.4862x over previous
#include <cuda_runtime.h>
#include <math.h>
#include <float.h>

#define NN   8400
#define CC   80
#define RB   17      // REG_MAX+1 bins
#define KTOP 13
#define EPSF 1e-9f
#define MAXB 32
#define MAXM 96
#define CAP  1536
#define CLS_BLKS 1024
#define HSH  2048

// ---------------- scratch (static device globals; all zero-init) ----------
__device__ float4             g_boxes4[MAXB * NN];
__device__ unsigned long long g_key[MAXB * NN];     // (metric_bits<<32)|(~m); self-cleaned
__device__ int                g_tk_n[MAXB * MAXM * KTOP];
__device__ float              g_tk_v[MAXB * MAXM * KTOP];
__device__ float              g_gt_mm[MAXB * MAXM];
__device__ float              g_gt_mi[MAXB * MAXM];
__device__ int                g_fgl[MAXB * MAXM * KTOP];           // pick anchor idx
__device__ unsigned long long g_fgv[MAXB * MAXM * KTOP];           // pick key
__device__ int                g_fgcnt;
__device__ int                g_done;
__device__ double             g_acc[8]; // 0 cls_base, 1 cls_corr, 2 score_sum, 3 iou, 4 dfl, 5 npos

__device__ __forceinline__ void warp_add(double v, double* gaddr) {
#pragma unroll
    for (int off = 16; off; off >>= 1)
        v += __shfl_down_sync(0xFFFFFFFFu, v, off);
    if ((threadIdx.x & 31) == 0) atomicAdd(gaddr, v);
}
__device__ __forceinline__ void sig_bce0(float x, float& sg, float& bce0) {
    float u = __expf(-fabsf(x));
    float r = __fdividef(1.f, 1.f + u);
    sg   = (x >= 0.f) ? r : 1.f - r;
    bce0 = fmaxf(x, 0.f) + __logf(1.f + u);
}

// ---------------- K1: DFL box decode (one thread per anchor) --------------
__global__ void k_decode(const float* __restrict__ pd, const float* __restrict__ ap, int total) {
    int an = blockIdx.x * blockDim.x + threadIdx.x;
    if (an >= total) return;
    int n = an % NN;
    const float4* row4 = (const float4*)(pd + (size_t)an * (4 * RB));
    float r[4 * RB];
#pragma unroll
    for (int j = 0; j < RB; j++) {
        float4 v = row4[j];
        r[4 * j] = v.x; r[4 * j + 1] = v.y; r[4 * j + 2] = v.z; r[4 * j + 3] = v.w;
    }
    float d[4];
#pragma unroll
    for (int s = 0; s < 4; s++) {
        float mx = r[RB * s];
#pragma unroll
        for (int j = 1; j < RB; j++) mx = fmaxf(mx, r[RB * s + j]);
        float se = 0.f, ws = 0.f;
#pragma unroll
        for (int j = 0; j < RB; j++) {
            float e = __expf(r[RB * s + j] - mx);
            se += e; ws = fmaf(e, (float)j, ws);
        }
        d[s] = __fdividef(ws, se);
    }
    float axp = ap[2 * n], ayp = ap[2 * n + 1];
    float4 o; o.x = axp - d[0]; o.y = ayp - d[1]; o.z = axp + d[2]; o.w = ayp + d[3];
    g_boxes4[an] = o;
}

// ---------------- K2: [assign blocks | cls blocks] ------------------------
__global__ void k_mid(const float* __restrict__ scores, const int* __restrict__ gtl,
                      const float* __restrict__ gtb, const float* __restrict__ mgt,
                      int M, int nasn, long total4) {
    if ((int)blockIdx.x < nasn) {
        // ---------- TAL assignment, one block per (b,m) ----------
        __shared__ float s_iou[CAP];
        __shared__ unsigned long long s_key[CAP];
        __shared__ int   s_cnt;
        __shared__ int                pk_i[KTOP];
        __shared__ unsigned long long pk_k[KTOP];

        int b = blockIdx.x / M, m = blockIdx.x % M;
        int base = b * M + m;
        if (threadIdx.x == 0) s_cnt = 0;
        __syncthreads();

        float mg  = mgt[base];
        float gx1 = gtb[base * 4 + 0], gy1 = gtb[base * 4 + 1];
        float gx2 = gtb[base * 4 + 2], gy2 = gtb[base * 4 + 3];
        float ga  = (gx2 - gx1) * (gy2 - gy1);
        int   lbl = min(max(gtl[base], 0), CC - 1);

        const int   nlv[3] = { 80, 40, 20 };
        const int   off[3] = { 0, 6400, 8000 };
        const float sfv[3] = { 8.f, 16.f, 32.f };

        int xlo[3], ylo[3], wx[3], cbase[4];
        cbase[0] = 0;
#pragma unroll
        for (int l = 0; l < 3; l++) {
            float inv_s = 1.f / sfv[l];
            int n1 = nlv[l] - 1;
            int x0 = min(max((int)floorf(gx1 * inv_s - 0.5f), 0), n1);
            int x1 = min(max((int)ceilf (gx2 * inv_s - 0.5f), 0), n1);
            int y0 = min(max((int)floorf(gy1 * inv_s - 0.5f), 0), n1);
            int y1 = min(max((int)ceilf (gy2 * inv_s - 0.5f), 0), n1);
            xlo[l] = x0; ylo[l] = y0; wx[l] = x1 - x0 + 1;
            int cl = (mg != 0.f) ? wx[l] * (y1 - y0 + 1) : 0;
            cbase[l + 1] = cbase[l] + cl;
        }
        int ctot = cbase[3];

        for (int t = threadIdx.x; t < ctot; t += blockDim.x) {
            int l = (t >= cbase[1]) + (t >= cbase[2]);
            int j = t - cbase[l];
            int ix = xlo[l] + j % wx[l];
            int iy = ylo[l] + j / wx[l];
            float s  = sfv[l];
            float ax = ((float)ix + 0.5f) * s;
            float ay = ((float)iy + 0.5f) * s;
            float mind = fminf(fminf(ax - gx1, ay - gy1), fminf(gx2 - ax, gy2 - ay));
            if (!(mind > EPSF)) continue;
            int n = off[l] + iy * nlv[l] + ix;
            float4 pb = g_boxes4[(size_t)b * NN + n];
            float iw = fminf(pb.z, gx2) - fmaxf(pb.x, gx1);
            float ih = fminf(pb.w, gy2) - fmaxf(pb.y, gy1);
            if (iw <= 0.f || ih <= 0.f) continue;
            float inter = iw * ih;
            float pa = (pb.z - pb.x) * (pb.w - pb.y);
            float iou = __fdividef(inter, pa + ga - inter + EPSF);
            float x = scores[((size_t)b * NN + n) * CC + lbl];
            float u  = __expf(-fabsf(x));
            float r  = __fdividef(1.f, 1.f + u);
            float sc = (x >= 0.f) ? r : 1.f - r;
            float i2 = iou * iou;
            float met = sc * i2 * i2 * i2 * mg;
            if (met > 0.f) {
                int slot = atomicAdd(&s_cnt, 1);
                if (slot < CAP) {
                    s_iou[slot] = iou;
                    s_key[slot] = ((unsigned long long)__float_as_uint(met) << 32) |
                                  (unsigned long long)(0xFFFFFFFFu - (unsigned)n);
                }
            }
        }
        __syncthreads();
        int cnt = min(s_cnt, CAP);

        if (threadIdx.x < 32) {
            int lane = threadIdx.x;
            unsigned long long pkey = ~0ull;
            float mm = 0.f, mi = 0.f;
            int npk = 0;
            for (int k = 0; k < KTOP; k++) {
                unsigned long long bk = 0ull; int bi = -1;
                for (int j = lane; j < cnt; j += 32) {
                    unsigned long long kk = s_key[j];
                    if (kk < pkey && kk > bk) { bk = kk; bi = j; }
                }
#pragma unroll
                for (int off2 = 16; off2; off2 >>= 1) {
                    unsigned long long k2 = __shfl_down_sync(0xFFFFFFFFu, bk, off2);
                    int               i2 = __shfl_down_sync(0xFFFFFFFFu, bi, off2);
                    if (k2 > bk) { bk = k2; bi = i2; }
                }
                bk = __shfl_sync(0xFFFFFFFFu, bk, 0);
                bi = __shfl_sync(0xFFFFFFFFu, bi, 0);
                bool valid = (bk >> 32) != 0ull;
                if (lane == 0) {
                    if (valid) {
                        float met = __uint_as_float((unsigned)(bk >> 32));
                        int   n   = (int)(0xFFFFFFFFu - (unsigned)(bk & 0xFFFFFFFFull));
                        g_tk_v[base * KTOP + k] = met;
                        g_tk_n[base * KTOP + k] = n;
                        if (k == 0) mm = met;
                        mi = fmaxf(mi, s_iou[bi]);
                        unsigned long long mkey =
                            (bk & 0xFFFFFFFF00000000ull) |
                            (unsigned long long)(0xFFFFFFFFu - (unsigned)m);
                        atomicMax(&g_key[(size_t)b * NN + n], mkey);
                        pk_i[npk] = b * NN + n;
                        pk_k[npk] = mkey;
                        npk++;
                    } else {
                        g_tk_v[base * KTOP + k] = 0.f;
                        g_tk_n[base * KTOP + k] = -1;
                    }
                }
                if (valid) pkey = bk;
            }
            npk = __shfl_sync(0xFFFFFFFFu, npk, 0);
            int base2 = 0;
            if (lane == 0) {
                g_gt_mm[base] = mm; g_gt_mi[base] = mi;
                base2 = atomicAdd(&g_fgcnt, npk);
            }
            base2 = __shfl_sync(0xFFFFFFFFu, base2, 0);
            __syncwarp();
            if (lane < npk) {
                g_fgl[base2 + lane] = pk_i[lane];
                g_fgv[base2 + lane] = pk_k[lane];
            }
        }
    } else {
        // ---------- base VFL over all (b,n,c): one atomic per block ----------
        __shared__ double red[8];
        const float4* s4 = (const float4*)scores;
        float acc = 0.f;
        long stride = (long)CLS_BLKS * blockDim.x;
        for (long i = (long)(blockIdx.x - nasn) * blockDim.x + threadIdx.x;
             i < total4; i += stride) {
            float4 v = s4[i];
            float xs[4] = { v.x, v.y, v.z, v.w };
#pragma unroll
            for (int j = 0; j < 4; j++) {
                float sg, bb;
                sig_bce0(xs[j], sg, bb);
                acc = fmaf(sg * sg, bb, acc);
            }
        }
        double dv = (double)acc;
#pragma unroll
        for (int off = 16; off; off >>= 1)
            dv += __shfl_down_sync(0xFFFFFFFFu, dv, off);
        if ((threadIdx.x & 31) == 0) red[threadIdx.x >> 5] = dv;
        __syncthreads();
        if (threadIdx.x < 32) {
            double w = (threadIdx.x < 8) ? red[threadIdx.x] : 0.0;
#pragma unroll
            for (int off = 4; off; off >>= 1)
                w += __shfl_down_sync(0xFFFFFFFFu, w, off);
            if (threadIdx.x == 0) atomicAdd(&g_acc[0], 0.75 * w);
        }
    }
}

// ---------------- K3: post = GIoU+DFL | VFL corrections | finalize --------
__global__ void k_post(const float* __restrict__ pd, const float* __restrict__ ap,
                       const float* __restrict__ scores, const int* __restrict__ gtl,
                       const float* __restrict__ gtb, int M, int fgblks, float* out) {
    if ((int)blockIdx.x < fgblks) {
        int t = blockIdx.x * blockDim.x + threadIdx.x;
        double li = 0.0, ldf = 0.0, np = 0.0;
        if (t < g_fgcnt) {
            int i = g_fgl[t];
            unsigned long long mykey = g_fgv[t];
            if (g_key[i] == mykey) {                 // this pick is the argmax winner
                np = 1.0;
                int b = i / NN, n = i % NN;
                unsigned mstar = 0xFFFFFFFFu - (unsigned)(mykey & 0xFFFFFFFFull);
                const float* gt = &gtb[((size_t)b * M + mstar) * 4];
                float tx1 = gt[0], ty1 = gt[1], tx2 = gt[2], ty2 = gt[3];
                float4 p = g_boxes4[i];
                float iw = fminf(p.z, tx2) - fmaxf(p.x, tx1);
                float ih = fminf(p.w, ty2) - fmaxf(p.y, ty1);
                float inter = fmaxf(iw, 0.f) * fmaxf(ih, 0.f);
                float a1 = (p.z - p.x) * (p.w - p.y);
                float a2 = (tx2 - tx1) * (ty2 - ty1);
                float uni = a1 + a2 - inter;
                float iou = __fdividef(inter, uni + 1e-9f);
                float enc = (fmaxf(p.z, tx2) - fminf(p.x, tx1)) *
                            (fmaxf(p.w, ty2) - fminf(p.y, ty1));
                float giou = iou - __fdividef(enc - uni, enc + 1e-9f);
                li = (double)(1.f - giou);

                float axp = ap[2 * n], ayp = ap[2 * n + 1];
                float tt[4] = { axp - tx1, ayp - ty1, tx2 - axp, ty2 - ayp };
                float dfl = 0.f;
#pragma unroll
                for (int s = 0; s < 4; s++) {
                    const float* row = pd + (size_t)i * (4 * RB) + RB * s;
                    float rr[RB];
#pragma unroll
                    for (int j = 0; j < RB; j++) rr[j] = row[j];
                    float tv = fminf(fmaxf(tt[s], 0.f), 15.99f);
                    int tl = (int)floorf(tv);
                    float wr = tv - (float)tl, wl = 1.f - wr;
                    float mx = rr[0];
#pragma unroll
                    for (int j = 1; j < RB; j++) mx = fmaxf(mx, rr[j]);
                    float se = 0.f;
#pragma unroll
                    for (int j = 0; j < RB; j++) se += __expf(rr[j] - mx);
                    float lse = mx + __logf(se);
                    float cl = row[tl];       // L1-hot dynamic reads
                    float cr = row[tl + 1];
                    dfl += (lse - cl) * wl + (lse - cr) * wr;
                }
                ldf = (double)dfl;
            }
        }
        warp_add(li,  &g_acc[3]);
        warp_add(ldf, &g_acc[4]);
        warp_add(np,  &g_acc[5]);
    } else {
        // ---------- VFL corrections: one block per batch, hash dedupe ----------
        __shared__ float e_s[MAXM * KTOP];
        __shared__ int   e_nc[MAXM * KTOP];
        __shared__ int                h_key[HSH];
        __shared__ unsigned long long h_val[HSH];
        int b   = blockIdx.x - fgblks;
        int tot = M * KTOP;

        for (int i = threadIdx.x; i < HSH; i += blockDim.x) {
            h_key[i] = -1; h_val[i] = 0ull;
        }
        for (int i = threadIdx.x; i < tot; i += blockDim.x) {
            int mm = i / KTOP;
            int gi = (b * M + mm) * KTOP + (i % KTOP);
            float met = g_tk_v[gi];
            float s = -1.f; int nc = -1;
            if (met > 0.f) {
                s  = __fdividef(met, g_gt_mm[b * M + mm] + EPSF) * g_gt_mi[b * M + mm];
                nc = (g_tk_n[gi] << 7) | min(max(gtl[b * M + mm], 0), CC - 1);
            }
            e_s[i] = s; e_nc[i] = nc;
        }
        __syncthreads();

        // insert: max s wins; tie -> smaller i (packed ~i)
        for (int i = threadIdx.x; i < tot; i += blockDim.x) {
            float s = e_s[i];
            if (s < 0.f) continue;
            int nc = e_nc[i];
            unsigned long long pk = ((unsigned long long)__float_as_uint(s) << 32) |
                                    (unsigned long long)(0xFFFFFFFFu - (unsigned)i);
            unsigned p = ((unsigned)nc * 2654435761u) & (HSH - 1);
            for (;;) {
                int k = atomicCAS(&h_key[p], -1, nc);
                if (k == -1 || k == nc) { atomicMax(&h_val[p], pk); break; }
                p = (p + 1) & (HSH - 1);
            }
        }
        __syncthreads();

        double corr = 0.0, ssum = 0.0;
        for (int i = threadIdx.x; i < tot; i += blockDim.x) {
            float s = e_s[i];
            if (s < 0.f) continue;
            int nc = e_nc[i];
            unsigned long long pk = ((unsigned long long)__float_as_uint(s) << 32) |
                                    (unsigned long long)(0xFFFFFFFFu - (unsigned)i);
            unsigned p = ((unsigned)nc * 2654435761u) & (HSH - 1);
            while (h_key[p] != nc) p = (p + 1) & (HSH - 1);
            if (h_val[p] != pk) continue;           // not the owner of this (n,c)
            int n = nc >> 7, c = nc & 127;
            unsigned long long key = g_key[(size_t)b * NN + n];
            unsigned mstar = 0xFFFFFFFFu - (unsigned)(key & 0xFFFFFFFFull);
            int albl = min(max(gtl[b * M + mstar], 0), CC - 1);
            float x = scores[((size_t)b * NN + n) * CC + c];
            float sg, bce0;
            sig_bce0(x, sg, bce0);
            float bce = bce0 - x * s;
            float wb  = 0.75f * sg * sg;
            float w   = (albl == c) ? s : wb;
            corr += (double)(w * bce) - (double)(wb * bce0);
            ssum += (double)s;
        }
        warp_add(corr, &g_acc[1]);
        warp_add(ssum, &g_acc[2]);
    }

    // ---- last-block finalize + self-clean ----
    __shared__ int s_last;
    __threadfence();
    __syncthreads();
    if (threadIdx.x == 0) {
        int ticket = atomicAdd(&g_done, 1);
        s_last = (ticket == (int)gridDim.x - 1);
    }
    __syncthreads();
    if (!s_last) return;
    __threadfence();
    if (threadIdx.x == 0) {
        volatile double* a = g_acc;
        double np = a[5] < 1.0 ? 1.0 : a[5];
        double ss = a[2] < 1.0 ? 1.0 : a[2];
        double loss = (a[0] + a[1]) / ss
                    + 2.5 * a[3] / np
                    + 0.5 * a[4] / (np * 4.0);
        out[0] = (float)loss;
    }
    __syncthreads();
    int fcnt = g_fgcnt;
    for (int t = threadIdx.x; t < fcnt; t += blockDim.x)
        g_key[g_fgl[t]] = 0ull;                        // clean touched keys
    __syncthreads();
    if (threadIdx.x < 8) g_acc[threadIdx.x] = 0.0;
    if (threadIdx.x == 8) g_fgcnt = 0;
    if (threadIdx.x == 9) g_done = 0;
}

// ---------------- launcher (3 launches) -----------------------------------
extern "C" void kernel_launch(void* const* d_in, const int* in_sizes, int n_in,
                              void* d_out, int out_size) {
    const float* scores = (const float*)d_in[0];
    const float* pdist  = (const float*)d_in[1];
    const float* ap     = (const float*)d_in[2];
    const int*   gtl    = (const int*)d_in[3];
    const float* gtb    = (const float*)d_in[4];
    const float* mgt    = (const float*)d_in[5];

    int B = in_sizes[0] / (NN * CC);
    int M = in_sizes[4] / (B * 4);
    int total = B * NN;
    long total4 = (long)total * CC / 4;
    int nasn   = B * M;
    int maxfg  = B * M * KTOP;
    int fgblks = (maxfg + 255) / 256;

    k_decode<<<(total + 255) / 256, 256>>>(pdist, ap, total);
    k_mid<<<nasn + CLS_BLKS, 256>>>(scores, gtl, gtb, mgt, M, nasn, total4);
    k_post<<<fgblks + B, 256>>>(pdist, ap, scores, gtl, gtb, M, fgblks, (float*)d_out);
}